// round 9
// baseline (speedup 1.0000x reference)
#include <cuda_runtime.h>

// ---------------------------------------------------------------------------
// GCN 2-layer: out = A_hat(relu(A_hat(x@W1)+b1) @ W2) + b2
// CSR-gather design (R6/R7) + f32x2-packed GEMM1 with W-from-L1 (R9).
// ---------------------------------------------------------------------------

#define MAX_N 100000
#define MAX_E 3200000
#define F_IN  512
#define HID   16
#define CLS   7

#define SCAN_B 1024
#define MAX_PART 128   // ceil(MAX_N / SCAN_B) = 98

// Scratch (device globals: allocation-free rule).
__device__ __align__(16) int   g_degi  [MAX_N];
__device__ __align__(16) float g_dinv  [MAX_N];
__device__ __align__(16) int   g_rowptr[MAX_N + 1];
__device__ __align__(16) int   g_cursor[MAX_N];
__device__ __align__(16) int   g_part  [MAX_PART];
__device__ __align__(16) int   g_partpre[MAX_PART];
__device__ __align__(16) int2  g_csr   [MAX_E];       // {src, __float_as_int(w)}
__device__ __align__(16) float g_h     [MAX_N * HID]; // x @ W1
__device__ __align__(16) float g_hagg  [MAX_N * HID]; // aggregated layer-1
__device__ __align__(16) float g_h2    [MAX_N * CLS]; // relu(hagg+b1) @ W2
__device__ int g_is64;                                 // edge_index dtype flag

// ---- f32x2 helpers (sm_103a packed fp32 pipe) ------------------------------
__device__ __forceinline__ void ffma2(unsigned long long& d,
                                      unsigned long long a,
                                      unsigned long long b) {
    asm("fma.rn.f32x2 %0, %1, %2, %0;" : "+l"(d) : "l"(a), "l"(b));
}
__device__ __forceinline__ unsigned long long pack2(float lo, float hi) {
    unsigned long long r;
    asm("mov.b64 %0, {%1, %2};" : "=l"(r) : "r"(__float_as_uint(lo)), "r"(__float_as_uint(hi)));
    return r;
}
__device__ __forceinline__ unsigned long long bcast2(float v) {
    unsigned long long r;
    unsigned u = __float_as_uint(v);
    asm("mov.b64 %0, {%1, %1};" : "=l"(r) : "r"(u));
    return r;
}
__device__ __forceinline__ void unpack2(unsigned long long v, float& lo, float& hi) {
    unsigned a, b;
    asm("mov.b64 {%0, %1}, %2;" : "=r"(a), "=r"(b) : "l"(v));
    lo = __uint_as_float(a);
    hi = __uint_as_float(b);
}

// ---------------------------------------------------------------------------
// dtype probe: int64 interpretation valid iff all sampled values in [0, n).
__global__ void k_detect(const void* __restrict__ ei, int n) {
    if (blockIdx.x == 0 && threadIdx.x == 0) {
        const long long* p = (const long long*)ei;
        int ok = 1;
        #pragma unroll 1
        for (int i = 0; i < 64; i++) {
            long long v = p[i];
            if (v < 0 || v >= (long long)n) { ok = 0; break; }
        }
        g_is64 = ok;
    }
}

// ---------------------------------------------------------------------------
__global__ void k_zero_deg(int n) {
    int i = blockIdx.x * blockDim.x + threadIdx.x;
    if (i < n) g_degi[i] = 0;
}

// int histogram of dst; 2 edges per thread (vectorized index load).
__global__ void k_deg(const void* __restrict__ ei, int E, int n) {
    int e = (blockIdx.x * blockDim.x + threadIdx.x) * 2;
    if (e >= E) return;
    int d0, d1 = -1;
    if (g_is64) {
        const long long* p = (const long long*)ei + E;   // dst row
        if (e + 1 < E) {
            longlong2 v = *(const longlong2*)(p + e);
            d0 = (int)v.x; d1 = (int)v.y;
        } else d0 = (int)p[e];
    } else {
        const int* p = (const int*)ei + E;
        if (e + 1 < E) {
            int2 v = *(const int2*)(p + e);
            d0 = v.x; d1 = v.y;
        } else d0 = p[e];
    }
    if ((unsigned)d0 < (unsigned)n) atomicAdd(&g_degi[d0], 1);
    if ((unsigned)d1 < (unsigned)n) atomicAdd(&g_degi[d1], 1);
}

// ---------------------------------------------------------------------------
// Multi-block exclusive scan, phase 1: per-block (1024-chunk) sums.
__global__ void __launch_bounds__(SCAN_B) k_part(int n) {
    __shared__ int sd[SCAN_B];
    int t = threadIdx.x;
    int i = blockIdx.x * SCAN_B + t;
    sd[t] = (i < n) ? g_degi[i] : 0;
    __syncthreads();
    #pragma unroll
    for (int off = SCAN_B / 2; off > 0; off >>= 1) {
        if (t < off) sd[t] += sd[t + off];
        __syncthreads();
    }
    if (t == 0) g_part[blockIdx.x] = sd[0];
}

// Phase 2: single small block scans the partials (nb <= MAX_PART).
__global__ void __launch_bounds__(MAX_PART) k_scanpart(int nb, int n) {
    __shared__ int sd[MAX_PART];
    int t = threadIdx.x;
    int v = (t < nb) ? g_part[t] : 0;
    sd[t] = v;
    __syncthreads();
    #pragma unroll
    for (int off = 1; off < MAX_PART; off <<= 1) {
        int a = sd[t];
        int b = (t >= off) ? sd[t - off] : 0;
        __syncthreads();
        sd[t] = a + b;
        __syncthreads();
    }
    if (t < nb) g_partpre[t] = sd[t] - v;       // exclusive prefix
    if (t == MAX_PART - 1) g_rowptr[n] = sd[MAX_PART - 1];
}

// Phase 3: in-block exclusive scan + block offset; fused dinv.
__global__ void __launch_bounds__(SCAN_B) k_scanfinal(int n) {
    __shared__ int sd[SCAN_B];
    int t = threadIdx.x;
    int i = blockIdx.x * SCAN_B + t;
    int v = (i < n) ? g_degi[i] : 0;
    sd[t] = v;
    __syncthreads();
    #pragma unroll
    for (int off = 1; off < SCAN_B; off <<= 1) {
        int a = sd[t];
        int b = (t >= off) ? sd[t - off] : 0;
        __syncthreads();
        sd[t] = a + b;
        __syncthreads();
    }
    if (i < n) {
        int pos = g_partpre[blockIdx.x] + sd[t] - v;
        g_rowptr[i] = pos;
        g_cursor[i] = pos;
        g_dinv[i]   = rsqrtf((float)(v + 1));   // +1 self loop
    }
}

// ---------------------------------------------------------------------------
// Scatter edges into CSR slots; 2 edges per thread (vectorized index load).
__global__ void k_scatter(const void* __restrict__ ei, int E, int n) {
    int e = (blockIdx.x * blockDim.x + threadIdx.x) * 2;
    if (e >= E) return;
    int s0, d0, s1 = -1, d1 = -1;
    if (g_is64) {
        const long long* ps = (const long long*)ei;
        const long long* pd = ps + E;
        if (e + 1 < E) {
            longlong2 vs = *(const longlong2*)(ps + e);
            longlong2 vd = *(const longlong2*)(pd + e);
            s0 = (int)vs.x; s1 = (int)vs.y;
            d0 = (int)vd.x; d1 = (int)vd.y;
        } else { s0 = (int)ps[e]; d0 = (int)pd[e]; }
    } else {
        const int* ps = (const int*)ei;
        const int* pd = ps + E;
        if (e + 1 < E) {
            int2 vs = *(const int2*)(ps + e);
            int2 vd = *(const int2*)(pd + e);
            s0 = vs.x; s1 = vs.y; d0 = vd.x; d1 = vd.y;
        } else { s0 = ps[e]; d0 = pd[e]; }
    }
    if ((unsigned)s0 < (unsigned)n && (unsigned)d0 < (unsigned)n) {
        float w = g_dinv[s0] * g_dinv[d0];
        int pos = atomicAdd(&g_cursor[d0], 1);
        if (pos < MAX_E) g_csr[pos] = make_int2(s0, __float_as_int(w));
    }
    if ((unsigned)s1 < (unsigned)n && (unsigned)d1 < (unsigned)n) {
        float w = g_dinv[s1] * g_dinv[d1];
        int pos = atomicAdd(&g_cursor[d1], 1);
        if (pos < MAX_E) g_csr[pos] = make_int2(s1, __float_as_int(w));
    }
}

// ---------------------------------------------------------------------------
// GEMM1 v2: h = x @ W1   (M=n, K=512, N=16)
// 128 threads/block, 256 rows/block. Thread tile: 8 rows x 4 cols.
// Accumulators in packed f32x2 (fma.rn.f32x2: 2 fp32 FMA per instr).
// x staged in SMEM (KC=16 chunk, padded); W read straight from global
// (2KB hot chunk, L1-resident) to eliminate its SMEM phases.
#define G2_ROWS 256
#define G2_KC   16
#define G2_STR  20   // 16 + 4 pad

__global__ void __launch_bounds__(128) k_gemm1(
    const float* __restrict__ x, const float* __restrict__ W1, int n)
{
    __shared__ __align__(16) float xs[G2_ROWS * G2_STR];  // 20 KB

    const int t    = threadIdx.x;
    const int rg   = t >> 2;         // 0..31
    const int cg   = t & 3;          // 0..3 -> cols cg*4..cg*4+3
    const int row0 = blockIdx.x * G2_ROWS;

    unsigned long long acc[8][2];
    #pragma unroll
    for (int r = 0; r < 8; r++) {
        acc[r][0] = 0ull; acc[r][1] = 0ull;
    }

    const float4* x4 = (const float4*)x;
    const float4* W4 = (const float4*)W1;

    for (int kc = 0; kc < F_IN / G2_KC; kc++) {
        __syncthreads();
        // Load x tile: 256 rows x 16 floats = 1024 float4, 8 per thread.
        #pragma unroll
        for (int i = 0; i < 8; i++) {
            int idx = t + i * 128;
            int r   = idx >> 2;
            int q   = idx & 3;
            int gr  = row0 + r;
            float4 v = make_float4(0.f, 0.f, 0.f, 0.f);
            if (gr < n) v = x4[gr * (F_IN / 4) + kc * (G2_KC / 4) + q];
            *(float4*)&xs[r * G2_STR + q * 4] = v;
        }
        __syncthreads();

        #pragma unroll
        for (int k4 = 0; k4 < G2_KC / 4; k4++) {
            const int kk = kc * G2_KC + k4 * 4;
            // W for k..k+3, this thread's 4 columns (global, L1-hot).
            float4 w0 = W4[(kk + 0) * 4 + cg];
            float4 w1 = W4[(kk + 1) * 4 + cg];
            float4 w2 = W4[(kk + 2) * 4 + cg];
            float4 w3 = W4[(kk + 3) * 4 + cg];
            unsigned long long wp[4][2];
            wp[0][0] = pack2(w0.x, w0.y); wp[0][1] = pack2(w0.z, w0.w);
            wp[1][0] = pack2(w1.x, w1.y); wp[1][1] = pack2(w1.z, w1.w);
            wp[2][0] = pack2(w2.x, w2.y); wp[2][1] = pack2(w2.z, w2.w);
            wp[3][0] = pack2(w3.x, w3.y); wp[3][1] = pack2(w3.z, w3.w);

            #pragma unroll
            for (int r = 0; r < 8; r++) {
                float4 xv = *(const float4*)&xs[(rg + 32 * r) * G2_STR + k4 * 4];
                unsigned long long x0 = bcast2(xv.x);
                unsigned long long x1 = bcast2(xv.y);
                unsigned long long x2 = bcast2(xv.z);
                unsigned long long x3 = bcast2(xv.w);
                ffma2(acc[r][0], x0, wp[0][0]);  ffma2(acc[r][1], x0, wp[0][1]);
                ffma2(acc[r][0], x1, wp[1][0]);  ffma2(acc[r][1], x1, wp[1][1]);
                ffma2(acc[r][0], x2, wp[2][0]);  ffma2(acc[r][1], x2, wp[2][1]);
                ffma2(acc[r][0], x3, wp[3][0]);  ffma2(acc[r][1], x3, wp[3][1]);
            }
        }
    }

    #pragma unroll
    for (int r = 0; r < 8; r++) {
        int gr = row0 + rg + 32 * r;
        if (gr < n) {
            float4 v;
            unpack2(acc[r][0], v.x, v.y);
            unpack2(acc[r][1], v.z, v.w);
            *(float4*)&g_h[gr * HID + cg * 4] = v;
        }
    }
}

// ---------------------------------------------------------------------------
// Layer-1 aggregation (gather, no atomics): 16 lanes per node.
__global__ void __launch_bounds__(256) k_agg1(int n)
{
    int id   = blockIdx.x * blockDim.x + threadIdx.x;
    int node = id >> 4;
    if (node >= n) return;
    int c = id & 15;

    int j   = g_rowptr[node];
    int end = g_rowptr[node + 1];

    float acc0 = 0.0f, acc1 = 0.0f;
    for (; j + 1 < end; j += 2) {
        int2 r0 = g_csr[j];
        int2 r1 = g_csr[j + 1];
        acc0 = fmaf(g_h[r0.x * HID + c], __int_as_float(r0.y), acc0);
        acc1 = fmaf(g_h[r1.x * HID + c], __int_as_float(r1.y), acc1);
    }
    if (j < end) {
        int2 r = g_csr[j];
        acc0 = fmaf(g_h[r.x * HID + c], __int_as_float(r.y), acc0);
    }

    float di = g_dinv[node];
    g_hagg[node * HID + c] = acc0 + acc1 + g_h[node * HID + c] * di * di;
}

// ---------------------------------------------------------------------------
// GEMM2: h2 = relu(hagg + b1) @ W2
__global__ void __launch_bounds__(256) k_gemm2(
    const float* __restrict__ b1, const float* __restrict__ W2, int n)
{
    __shared__ float W2s[HID * CLS];
    __shared__ float b1s[HID];
    int t = threadIdx.x;
    if (t < HID * CLS) W2s[t] = W2[t];
    if (t < HID)       b1s[t] = b1[t];
    __syncthreads();

    int i = blockIdx.x * blockDim.x + t;
    if (i >= n) return;

    float v[HID];
    #pragma unroll
    for (int q = 0; q < 4; q++) {
        float4 hv = *(const float4*)&g_hagg[i * HID + q * 4];
        v[q * 4 + 0] = fmaxf(hv.x + b1s[q * 4 + 0], 0.0f);
        v[q * 4 + 1] = fmaxf(hv.y + b1s[q * 4 + 1], 0.0f);
        v[q * 4 + 2] = fmaxf(hv.z + b1s[q * 4 + 2], 0.0f);
        v[q * 4 + 3] = fmaxf(hv.w + b1s[q * 4 + 3], 0.0f);
    }

    float o[CLS];
    #pragma unroll
    for (int c2 = 0; c2 < CLS; c2++) o[c2] = 0.0f;
    #pragma unroll
    for (int c = 0; c < HID; c++) {
        float xv = v[c];
        #pragma unroll
        for (int c2 = 0; c2 < CLS; c2++) o[c2] += xv * W2s[c * CLS + c2];
    }

    #pragma unroll
    for (int c2 = 0; c2 < CLS; c2++) g_h2[i * CLS + c2] = o[c2];
}

// ---------------------------------------------------------------------------
// Layer-2 aggregation (gather): 8 lanes per node (7 used).
__global__ void __launch_bounds__(256) k_agg2(
    const float* __restrict__ b2, float* __restrict__ out, int n)
{
    int id   = blockIdx.x * blockDim.x + threadIdx.x;
    int node = id >> 3;
    if (node >= n) return;
    int c = id & 7;
    if (c >= CLS) return;

    int j   = g_rowptr[node];
    int end = g_rowptr[node + 1];

    float acc0 = 0.0f, acc1 = 0.0f;
    for (; j + 1 < end; j += 2) {
        int2 r0 = g_csr[j];
        int2 r1 = g_csr[j + 1];
        acc0 = fmaf(g_h2[r0.x * CLS + c], __int_as_float(r0.y), acc0);
        acc1 = fmaf(g_h2[r1.x * CLS + c], __int_as_float(r1.y), acc1);
    }
    if (j < end) {
        int2 r = g_csr[j];
        acc0 = fmaf(g_h2[r.x * CLS + c], __int_as_float(r.y), acc0);
    }

    float di = g_dinv[node];
    out[node * CLS + c] = acc0 + acc1 + g_h2[node * CLS + c] * di * di + b2[c];
}

// ---------------------------------------------------------------------------
extern "C" void kernel_launch(void* const* d_in, const int* in_sizes, int n_in,
                              void* d_out, int out_size)
{
    // ---- identify inputs by element count ----
    int ix = -1, ie = -1, iw1 = -1, ib1 = -1, iw2 = -1, ib2 = -1;
    for (int i = 0; i < n_in; i++)
        if (ix < 0 || in_sizes[i] > in_sizes[ix]) ix = i;
    for (int i = 0; i < n_in; i++) {
        if (i == ix) continue;
        if (ie < 0 || in_sizes[i] > in_sizes[ie]) ie = i;
    }
    for (int i = 0; i < n_in; i++) {
        if (i == ix || i == ie) continue;
        if (in_sizes[i] == F_IN * HID) iw1 = i;
        else if (in_sizes[i] == HID * CLS) iw2 = i;
        else if (in_sizes[i] == HID) ib1 = i;
        else if (in_sizes[i] == CLS) ib2 = i;
    }
    if (ix < 0 || ie < 0 || iw1 < 0 || ib1 < 0 || iw2 < 0 || ib2 < 0) {
        ix = 0; ie = 1; iw1 = 2; ib1 = 3; iw2 = 4; ib2 = 5;
    }

    const float* x  = (const float*)d_in[ix];
    const void*  ei = d_in[ie];
    const float* W1 = (const float*)d_in[iw1];
    const float* b1 = (const float*)d_in[ib1];
    const float* W2 = (const float*)d_in[iw2];
    const float* b2 = (const float*)d_in[ib2];
    float* out = (float*)d_out;

    const int n = in_sizes[ix] / F_IN;   // 100000
    const int E = in_sizes[ie] / 2;      // 3200000

    const int TB = 256;
    const int nb = (n + SCAN_B - 1) / SCAN_B;   // 98

    k_detect<<<1, 32>>>(ei, n);

    // CSR build
    k_zero_deg<<<(n + TB - 1) / TB, TB>>>(n);
    {
        int nt = (E + 1) / 2;
        k_deg<<<(nt + TB - 1) / TB, TB>>>(ei, E, n);
    }
    k_part<<<nb, SCAN_B>>>(n);
    k_scanpart<<<1, MAX_PART>>>(nb, n);
    k_scanfinal<<<nb, SCAN_B>>>(n);
    {
        int nt = (E + 1) / 2;
        k_scatter<<<(nt + TB - 1) / TB, TB>>>(ei, E, n);
    }

    // layer 1
    k_gemm1<<<(n + G2_ROWS - 1) / G2_ROWS, 128>>>(x, W1, n);
    {
        long long work = (long long)n * 16;
        k_agg1<<<(int)((work + TB - 1) / TB), TB>>>(n);
    }

    // layer 2
    k_gemm2<<<(n + TB - 1) / TB, TB>>>(b1, W2, n);
    {
        long long work = (long long)n * 8;
        k_agg2<<<(int)((work + TB - 1) / TB), TB>>>(b2, out, n);
    }
}